// round 8
// baseline (speedup 1.0000x reference)
#include <cuda_runtime.h>
#include <cuda_fp16.h>
#include <cstdint>

#define N_NODES 100000
#define N_EDGES 800000
#define D 128
#define NCLS 64
#define NBLK 391    // ceil(N_NODES/256)
#define GBLK 782    // ceil(N_NODES/128)

// ---------------- scratch (static device globals; no allocation) ------------
__device__ __half g_xh [(size_t)N_NODES * D];
__device__ __half g_mh [(size_t)N_NODES * D];   // pooled features (ping)
__device__ __half g_mh2[(size_t)N_NODES * D];   // pooled features (pong)
__device__ __half g_h1h[(size_t)N_NODES * D];
__device__ __half g_h2h[(size_t)N_NODES * D];
__device__ int    g_row_start[N_NODES + 1];
__device__ int    g_next[N_NODES];
__device__ int    g_csr [N_EDGES];
__device__ int    g_partials[512];
// transposed fp16 weights, [N][K=128] layout, packed
__device__ __half g_wt[131072];

// ---------------- small helpers ---------------------------------------------
__device__ __forceinline__ uint32_t h2_bits(__half2 h) {
    return *reinterpret_cast<uint32_t*>(&h);
}
__device__ __forceinline__ __half2 bits_h2(uint32_t u) {
    return *reinterpret_cast<__half2*>(&u);
}

__device__ __forceinline__ void cp_async16(void* smem, const void* gmem, bool pred) {
    uint32_t s = (uint32_t)__cvta_generic_to_shared(smem);
    int sz = pred ? 16 : 0;
    asm volatile("cp.async.cg.shared.global [%0], [%1], 16, %2;\n" :: "r"(s), "l"(gmem), "r"(sz));
}

__device__ __forceinline__ void mma_f16(float c[4], const uint32_t a[4], const uint32_t b[2]) {
    asm volatile(
        "mma.sync.aligned.m16n8k16.row.col.f32.f16.f16.f32 "
        "{%0,%1,%2,%3}, {%4,%5,%6,%7}, {%8,%9}, {%0,%1,%2,%3};"
        : "+f"(c[0]), "+f"(c[1]), "+f"(c[2]), "+f"(c[3])
        : "r"(a[0]), "r"(a[1]), "r"(a[2]), "r"(a[3]), "r"(b[0]), "r"(b[1]));
}

// ---------------- merged prep: weights^T fp16 | x->fp16 | zero counts --------
__global__ void prep_kernel(
    const float* __restrict__ Wp0, const float* __restrict__ Wp1, const float* __restrict__ Wp2,
    const float* __restrict__ Ws0, const float* __restrict__ Ws1, const float* __restrict__ Ws2,
    const float* __restrict__ Wn0, const float* __restrict__ Wn1, const float* __restrict__ Wn2,
    const float4* __restrict__ x4)
{
    int b = blockIdx.x;
    if (b < 512) {
        int i = b * 256 + threadIdx.x;
        const float* src; int off; int N;
        if      (i <  16384) { src = Wp0; off = 0;      N = 128; }
        else if (i <  32768) { src = Wp1; off = 16384;  N = 128; }
        else if (i <  49152) { src = Wp2; off = 32768;  N = 128; }
        else if (i <  65536) { src = Ws0; off = 49152;  N = 128; }
        else if (i <  81920) { src = Ws1; off = 65536;  N = 128; }
        else if (i <  90112) { src = Ws2; off = 81920;  N = 64;  }
        else if (i < 106496) { src = Wn0; off = 90112;  N = 128; }
        else if (i < 122880) { src = Wn1; off = 106496; N = 128; }
        else                 { src = Wn2; off = 122880; N = 64;  }
        int li = i - off;
        int n = li >> 7, k = li & 127;
        g_wt[i] = __float2half(src[k * N + n]);
    } else if (b < 512 + 6250) {
        int i = (b - 512) * 256 + threadIdx.x;   // 8 floats per thread
        if (i < (N_NODES * D) / 8) {
            float4 a = __ldg(x4 + 2 * i);
            float4 c = __ldg(x4 + 2 * i + 1);
            uint4 o;
            o.x = h2_bits(__floats2half2_rn(a.x, a.y));
            o.y = h2_bits(__floats2half2_rn(a.z, a.w));
            o.z = h2_bits(__floats2half2_rn(c.x, c.y));
            o.w = h2_bits(__floats2half2_rn(c.z, c.w));
            ((uint4*)g_xh)[i] = o;
        }
    } else {
        int i = (b - 6762) * 256 + threadIdx.x;
        if (i < N_NODES) g_next[i] = 0;
    }
}

// ---------------- CSR build -------------------------------------------------
__global__ void hist_kernel(const int4* __restrict__ dst4) {
    int e = blockIdx.x * blockDim.x + threadIdx.x;
    if (e < N_EDGES / 4) {
        int4 d = __ldg(dst4 + e);
        atomicAdd(&g_next[d.x], 1);
        atomicAdd(&g_next[d.y], 1);
        atomicAdd(&g_next[d.z], 1);
        atomicAdd(&g_next[d.w], 1);
    }
}

__global__ void reduce_counts_kernel() {
    int i = blockIdx.x * 256 + threadIdx.x;
    int lane = threadIdx.x & 31, wid = threadIdx.x >> 5;
    int v = (i < N_NODES) ? g_next[i] : 0;
    #pragma unroll
    for (int o = 16; o; o >>= 1) v += __shfl_xor_sync(0xffffffffu, v, o);
    __shared__ int ws[8];
    if (lane == 0) ws[wid] = v;
    __syncthreads();
    if (threadIdx.x == 0) {
        int s = 0;
        #pragma unroll
        for (int j = 0; j < 8; j++) s += ws[j];
        g_partials[blockIdx.x] = s;
    }
}

__global__ void scan_partials_kernel() {
    int tid = threadIdx.x, lane = tid & 31, wid = tid >> 5;
    int v = (tid < NBLK) ? g_partials[tid] : 0;
    int incl = v;
    #pragma unroll
    for (int o = 1; o < 32; o <<= 1) {
        int n = __shfl_up_sync(0xffffffffu, incl, o);
        if (lane >= o) incl += n;
    }
    __shared__ int ws[16];
    if (lane == 31) ws[wid] = incl;
    __syncthreads();
    if (wid == 0) {
        int w = (lane < 16) ? ws[lane] : 0;
        int wi = w;
        #pragma unroll
        for (int o = 1; o < 16; o <<= 1) {
            int n = __shfl_up_sync(0xffffffffu, wi, o);
            if (lane >= o) wi += n;
        }
        if (lane < 16) ws[lane] = wi - w;
    }
    __syncthreads();
    int excl = ws[wid] + incl - v;
    if (tid < NBLK) g_partials[tid] = excl;
    if (tid == NBLK) g_row_start[N_NODES] = excl;
}

__global__ void write_offsets_kernel() {
    int i = blockIdx.x * 256 + threadIdx.x;
    int lane = threadIdx.x & 31, wid = threadIdx.x >> 5;
    int v = (i < N_NODES) ? g_next[i] : 0;
    int incl = v;
    #pragma unroll
    for (int o = 1; o < 32; o <<= 1) {
        int n = __shfl_up_sync(0xffffffffu, incl, o);
        if (lane >= o) incl += n;
    }
    __shared__ int ws[8];
    if (lane == 31) ws[wid] = incl;
    __syncthreads();
    if (wid == 0) {
        int w = (lane < 8) ? ws[lane] : 0;
        int wi = w;
        #pragma unroll
        for (int o = 1; o < 8; o <<= 1) {
            int n = __shfl_up_sync(0xffffffffu, wi, o);
            if (lane >= o) wi += n;
        }
        if (lane < 8) ws[lane] = wi - w;
    }
    __syncthreads();
    int excl = g_partials[blockIdx.x] + ws[wid] + incl - v;
    if (i < N_NODES) { g_row_start[i] = excl; g_next[i] = excl; }
}

__global__ void fill_kernel(const int4* __restrict__ src4, const int4* __restrict__ dst4) {
    int e = blockIdx.x * blockDim.x + threadIdx.x;
    if (e < N_EDGES / 4) {
        int4 s = __ldg(src4 + e);
        int4 d = __ldg(dst4 + e);
        g_csr[atomicAdd(&g_next[d.x], 1)] = s.x;
        g_csr[atomicAdd(&g_next[d.y], 1)] = s.y;
        g_csr[atomicAdd(&g_next[d.z], 1)] = s.z;
        g_csr[atomicAdd(&g_next[d.w], 1)] = s.w;
    }
}

// ---------------- pool0: single fp16 GEMM, m = relu(x@Wp0 + bp0) -------------
__global__ void __launch_bounds__(256)
pool_kernel(const __half* __restrict__ A, const __half* __restrict__ Bt,
            const float* __restrict__ bias, __half* __restrict__ C, int M)
{
    constexpr int ST = 20;
    __shared__ uint32_t As[2][128 * ST];
    __shared__ uint32_t Bs[2][128 * ST];

    const int tid = threadIdx.x;
    const int wid = tid >> 5;
    const int lane = tid & 31;
    const int g  = lane >> 2;
    const int tg = lane & 3;
    const int warpM = wid & 3;
    const int warpN = wid >> 2;
    const int rowBase = blockIdx.x * 128;

    float acc[2][8][4];
    #pragma unroll
    for (int mt = 0; mt < 2; mt++)
        #pragma unroll
        for (int nt = 0; nt < 8; nt++)
            #pragma unroll
            for (int q = 0; q < 4; q++) acc[mt][nt][q] = 0.f;

    auto load_stage = [&](int buf, int s) {
        int kk = s * 32;
        #pragma unroll
        for (int idx = tid; idx < 512; idx += 256) {
            int r = idx >> 2, c = idx & 3;
            bool p = (rowBase + r) < M;
            cp_async16(&As[buf][r * ST + c * 4], A + (size_t)(rowBase + r) * 128 + kk + c * 8, p);
        }
        #pragma unroll
        for (int idx = tid; idx < 512; idx += 256) {
            int n = idx >> 2, c = idx & 3;
            cp_async16(&Bs[buf][n * ST + c * 4], Bt + (size_t)n * 128 + kk + c * 8, true);
        }
        asm volatile("cp.async.commit_group;\n" ::);
    };

    load_stage(0, 0);
    for (int s = 0; s < 4; s++) {
        int buf = s & 1;
        if (s + 1 < 4) {
            load_stage(buf ^ 1, s + 1);
            asm volatile("cp.async.wait_group 1;\n" ::);
        } else {
            asm volatile("cp.async.wait_group 0;\n" ::);
        }
        __syncthreads();
        #pragma unroll
        for (int ks = 0; ks < 2; ks++) {
            uint32_t af[2][4];
            #pragma unroll
            for (int mt = 0; mt < 2; mt++) {
                int r0 = warpM * 32 + mt * 16 + g;
                af[mt][0] = As[buf][(r0    ) * ST + ks * 8 + tg    ];
                af[mt][1] = As[buf][(r0 + 8) * ST + ks * 8 + tg    ];
                af[mt][2] = As[buf][(r0    ) * ST + ks * 8 + tg + 4];
                af[mt][3] = As[buf][(r0 + 8) * ST + ks * 8 + tg + 4];
            }
            uint32_t bf[8][2];
            #pragma unroll
            for (int nt = 0; nt < 8; nt++) {
                int c0 = warpN * 64 + nt * 8 + g;
                bf[nt][0] = Bs[buf][c0 * ST + ks * 8 + tg    ];
                bf[nt][1] = Bs[buf][c0 * ST + ks * 8 + tg + 4];
            }
            #pragma unroll
            for (int mt = 0; mt < 2; mt++)
                #pragma unroll
                for (int nt = 0; nt < 8; nt++)
                    mma_f16(acc[mt][nt], af[mt], bf[nt]);
        }
        __syncthreads();
    }

    #pragma unroll
    for (int mt = 0; mt < 2; mt++) {
        int r0 = rowBase + warpM * 32 + mt * 16 + g;
        #pragma unroll
        for (int nt = 0; nt < 8; nt++) {
            int c0 = warpN * 64 + nt * 8 + tg * 2;
            float b0 = __ldg(bias + c0), b1 = __ldg(bias + c0 + 1);
            if (r0 < M)
                *(__half2*)(C + (size_t)r0 * 128 + c0) =
                    __floats2half2_rn(fmaxf(acc[mt][nt][0] + b0, 0.f), fmaxf(acc[mt][nt][1] + b1, 0.f));
            if (r0 + 8 < M)
                *(__half2*)(C + (size_t)(r0 + 8) * 128 + c0) =
                    __floats2half2_rn(fmaxf(acc[mt][nt][2] + b0, 0.f), fmaxf(acc[mt][nt][3] + b1, 0.f));
        }
    }
}

// ---------------- fused combine kernel ---------------------------------------
// Phase 0: gather agg tile from Min (segment-max over in-edges) -> smem
// Phase 1: dual GEMM  h = relu(Aprev@Ws^T + agg@Wn^T + bn)  [agg from smem]
// Phase 2 (POOL): m_next = relu(h@Wp^T + bp) with h in smem -> Mout (!= Min,
//         ping-pong buffers: phase-0 gathers of other blocks still read Min)
//         (!POOL): fused log-softmax -> Lout (BN=64)
template<int BN, bool POOL>
__global__ void __launch_bounds__(256)
comb_kernel(const __half* __restrict__ Min,
            const __half* __restrict__ Aprev, const __half* __restrict__ WsT,
            const __half* __restrict__ WnT,  const float* __restrict__ bn_,
            const __half* __restrict__ WpT,  const float* __restrict__ bp_,
            __half* __restrict__ Hout, __half* __restrict__ Mout,
            float* __restrict__ Lout, int M)
{
    constexpr int ST = 20;
    constexpr int FT = 68;                     // full-K tile stride (words), conflict-free
    constexpr int MT = (BN == 128) ? 2 : 1;
    constexpr int WM = MT * 16;
    extern __shared__ uint32_t smem[];
    uint32_t* fullT = smem;                    // 128*68 = 8704 words
    uint32_t* As    = smem + 8704;             // 2 * 2560
    uint32_t* Bs    = smem + 8704 + 5120;      // 2 * BN*20

    const int tid = threadIdx.x;
    const int wid = tid >> 5;
    const int lane = tid & 31;
    const int g  = lane >> 2;
    const int tg = lane & 3;
    const int warpM = (BN == 128) ? (wid & 3) : wid;
    const int warpN = (BN == 128) ? (wid >> 2) : 0;
    const int rowBase = blockIdx.x * 128;

    // ---- phase 0: gather agg tile into fullT (fp16, relu>=0 so init 0) ----
    {
        const uint2* mp = (const uint2*)Min;
        for (int r = wid; r < 128; r += 8) {
            int row = rowBase + r;
            __half2 a0 = __float2half2_rn(0.f), a1 = a0;
            if (row < M) {
                int s = __ldg(&g_row_start[row]);
                int e = __ldg(&g_row_start[row + 1]);
                int i = s;
                for (; i + 4 <= e; i += 4) {
                    int s0 = __ldg(&g_csr[i]),     s1 = __ldg(&g_csr[i + 1]);
                    int s2 = __ldg(&g_csr[i + 2]), s3 = __ldg(&g_csr[i + 3]);
                    uint2 v0 = __ldg(mp + (size_t)s0 * 32 + lane);
                    uint2 v1 = __ldg(mp + (size_t)s1 * 32 + lane);
                    uint2 v2 = __ldg(mp + (size_t)s2 * 32 + lane);
                    uint2 v3 = __ldg(mp + (size_t)s3 * 32 + lane);
                    a0 = __hmax2(a0, __hmax2(__hmax2(bits_h2(v0.x), bits_h2(v1.x)),
                                             __hmax2(bits_h2(v2.x), bits_h2(v3.x))));
                    a1 = __hmax2(a1, __hmax2(__hmax2(bits_h2(v0.y), bits_h2(v1.y)),
                                             __hmax2(bits_h2(v2.y), bits_h2(v3.y))));
                }
                for (; i < e; i++) {
                    int s0 = __ldg(&g_csr[i]);
                    uint2 v0 = __ldg(mp + (size_t)s0 * 32 + lane);
                    a0 = __hmax2(a0, bits_h2(v0.x));
                    a1 = __hmax2(a1, bits_h2(v0.y));
                }
            }
            uint2 o; o.x = h2_bits(a0); o.y = h2_bits(a1);
            *(uint2*)&fullT[r * FT + lane * 2] = o;
        }
    }
    __syncthreads();

    // ---- phase 1: dual GEMM ----
    float acc[MT][8][4];
    #pragma unroll
    for (int mt = 0; mt < MT; mt++)
        #pragma unroll
        for (int nt = 0; nt < 8; nt++)
            #pragma unroll
            for (int q = 0; q < 4; q++) acc[mt][nt][q] = 0.f;

    auto load_stage = [&](int buf, int s) {
        if (s < 4) {
            int kk = s * 32;
            #pragma unroll
            for (int idx = tid; idx < 512; idx += 256) {
                int r = idx >> 2, c = idx & 3;
                bool p = (rowBase + r) < M;
                cp_async16(&As[buf * 2560 + r * ST + c * 4],
                           Aprev + (size_t)(rowBase + r) * 128 + kk + c * 8, p);
            }
            #pragma unroll
            for (int idx = tid; idx < BN * 4; idx += 256) {
                int n = idx >> 2, c = idx & 3;
                cp_async16(&Bs[buf * BN * ST + n * ST + c * 4],
                           WsT + (size_t)n * 128 + kk + c * 8, true);
            }
        } else {
            int kk = (s - 4) * 32;
            #pragma unroll
            for (int idx = tid; idx < BN * 4; idx += 256) {
                int n = idx >> 2, c = idx & 3;
                cp_async16(&Bs[buf * BN * ST + n * ST + c * 4],
                           WnT + (size_t)n * 128 + kk + c * 8, true);
            }
        }
        asm volatile("cp.async.commit_group;\n" ::);
    };

    load_stage(0, 0);
    #pragma unroll 1
    for (int s = 0; s < 8; s++) {
        int buf = s & 1;
        if (s + 1 < 8) {
            load_stage(buf ^ 1, s + 1);
            asm volatile("cp.async.wait_group 1;\n" ::);
        } else {
            asm volatile("cp.async.wait_group 0;\n" ::);
        }
        __syncthreads();
        const bool passA = (s < 4);
        const uint32_t* ap = passA ? (As + buf * 2560) : (fullT + (s - 4) * 16);
        const int astr = passA ? ST : FT;
        #pragma unroll
        for (int ks = 0; ks < 2; ks++) {
            uint32_t af[MT][4];
            #pragma unroll
            for (int mt = 0; mt < MT; mt++) {
                int r0 = warpM * WM + mt * 16 + g;
                af[mt][0] = ap[(r0    ) * astr + ks * 8 + tg    ];
                af[mt][1] = ap[(r0 + 8) * astr + ks * 8 + tg    ];
                af[mt][2] = ap[(r0    ) * astr + ks * 8 + tg + 4];
                af[mt][3] = ap[(r0 + 8) * astr + ks * 8 + tg + 4];
            }
            uint32_t bf[8][2];
            #pragma unroll
            for (int nt = 0; nt < 8; nt++) {
                int c0 = warpN * 64 + nt * 8 + g;
                const uint32_t* bp2 = Bs + buf * BN * ST;
                bf[nt][0] = bp2[c0 * ST + ks * 8 + tg    ];
                bf[nt][1] = bp2[c0 * ST + ks * 8 + tg + 4];
            }
            #pragma unroll
            for (int mt = 0; mt < MT; mt++)
                #pragma unroll
                for (int nt = 0; nt < 8; nt++)
                    mma_f16(acc[mt][nt], af[mt], bf[nt]);
        }
        __syncthreads();
    }

    if (!POOL) {
        // fused log-softmax epilogue (BN == 64)
        float v0[16], v1[16];
        #pragma unroll
        for (int nt = 0; nt < 8; nt++) {
            int c0 = nt * 8 + tg * 2;
            float b0 = __ldg(bn_ + c0), b1 = __ldg(bn_ + c0 + 1);
            v0[nt * 2    ] = fmaxf(acc[0][nt][0] + b0, 0.f);
            v0[nt * 2 + 1] = fmaxf(acc[0][nt][1] + b1, 0.f);
            v1[nt * 2    ] = fmaxf(acc[0][nt][2] + b0, 0.f);
            v1[nt * 2 + 1] = fmaxf(acc[0][nt][3] + b1, 0.f);
        }
        float mx0 = v0[0], mx1 = v1[0];
        #pragma unroll
        for (int i = 1; i < 16; i++) { mx0 = fmaxf(mx0, v0[i]); mx1 = fmaxf(mx1, v1[i]); }
        #pragma unroll
        for (int o = 1; o <= 2; o <<= 1) {
            mx0 = fmaxf(mx0, __shfl_xor_sync(0xffffffffu, mx0, o));
            mx1 = fmaxf(mx1, __shfl_xor_sync(0xffffffffu, mx1, o));
        }
        float s0 = 0.f, s1 = 0.f;
        #pragma unroll
        for (int i = 0; i < 16; i++) { s0 += expf(v0[i] - mx0); s1 += expf(v1[i] - mx1); }
        #pragma unroll
        for (int o = 1; o <= 2; o <<= 1) {
            s0 += __shfl_xor_sync(0xffffffffu, s0, o);
            s1 += __shfl_xor_sync(0xffffffffu, s1, o);
        }
        float l0 = mx0 + logf(s0), l1 = mx1 + logf(s1);
        int r0 = rowBase + warpM * 16 + g;
        #pragma unroll
        for (int nt = 0; nt < 8; nt++) {
            int c0 = nt * 8 + tg * 2;
            if (r0 < M)
                *(float2*)(Lout + (size_t)r0 * 64 + c0) =
                    make_float2(v0[nt * 2] - l0, v0[nt * 2 + 1] - l0);
            if (r0 + 8 < M)
                *(float2*)(Lout + (size_t)(r0 + 8) * 64 + c0) =
                    make_float2(v1[nt * 2] - l1, v1[nt * 2 + 1] - l1);
        }
        return;
    }

    // ---- dual epilogue: h -> fullT (smem) + Hout (gmem) ----
    #pragma unroll
    for (int mt = 0; mt < MT; mt++) {
        int rl = warpM * WM + mt * 16 + g;
        int r0 = rowBase + rl;
        #pragma unroll
        for (int nt = 0; nt < 8; nt++) {
            int c0 = warpN * 64 + nt * 8 + tg * 2;
            float b0 = __ldg(bn_ + c0), b1 = __ldg(bn_ + c0 + 1);
            __half2 h0 = __floats2half2_rn(fmaxf(acc[mt][nt][0] + b0, 0.f),
                                           fmaxf(acc[mt][nt][1] + b1, 0.f));
            __half2 h1 = __floats2half2_rn(fmaxf(acc[mt][nt][2] + b0, 0.f),
                                           fmaxf(acc[mt][nt][3] + b1, 0.f));
            fullT[rl * FT + (c0 >> 1)]       = h2_bits(h0);
            fullT[(rl + 8) * FT + (c0 >> 1)] = h2_bits(h1);
            if (r0 < M)     *(__half2*)(Hout + (size_t)r0 * 128 + c0)       = h0;
            if (r0 + 8 < M) *(__half2*)(Hout + (size_t)(r0 + 8) * 128 + c0) = h1;
        }
    }
    __syncthreads();

    // ---- phase 2: pool GEMM  m = relu(h@Wp^T + bp), A = h tile in smem ----
    #pragma unroll
    for (int mt = 0; mt < MT; mt++)
        #pragma unroll
        for (int nt = 0; nt < 8; nt++)
            #pragma unroll
            for (int q = 0; q < 4; q++) acc[mt][nt][q] = 0.f;

    auto load_pool = [&](int buf, int s) {
        int kk = s * 32;
        #pragma unroll
        for (int idx = tid; idx < 512; idx += 256) {
            int n = idx >> 2, c = idx & 3;
            cp_async16(&Bs[buf * BN * ST + n * ST + c * 4],
                       WpT + (size_t)n * 128 + kk + c * 8, true);
        }
        asm volatile("cp.async.commit_group;\n" ::);
    };

    load_pool(0, 0);
    #pragma unroll 1
    for (int s = 0; s < 4; s++) {
        int buf = s & 1;
        if (s + 1 < 4) {
            load_pool(buf ^ 1, s + 1);
            asm volatile("cp.async.wait_group 1;\n" ::);
        } else {
            asm volatile("cp.async.wait_group 0;\n" ::);
        }
        __syncthreads();
        const uint32_t* ap = fullT + s * 16;
        #pragma unroll
        for (int ks = 0; ks < 2; ks++) {
            uint32_t af[MT][4];
            #pragma unroll
            for (int mt = 0; mt < MT; mt++) {
                int r0 = warpM * WM + mt * 16 + g;
                af[mt][0] = ap[(r0    ) * FT + ks * 8 + tg    ];
                af[mt][1] = ap[(r0 + 8) * FT + ks * 8 + tg    ];
                af[mt][2] = ap[(r0    ) * FT + ks * 8 + tg + 4];
                af[mt][3] = ap[(r0 + 8) * FT + ks * 8 + tg + 4];
            }
            uint32_t bf[8][2];
            #pragma unroll
            for (int nt = 0; nt < 8; nt++) {
                int c0 = warpN * 64 + nt * 8 + g;
                const uint32_t* bp2 = Bs + buf * BN * ST;
                bf[nt][0] = bp2[c0 * ST + ks * 8 + tg    ];
                bf[nt][1] = bp2[c0 * ST + ks * 8 + tg + 4];
            }
            #pragma unroll
            for (int mt = 0; mt < MT; mt++)
                #pragma unroll
                for (int nt = 0; nt < 8; nt++)
                    mma_f16(acc[mt][nt], af[mt], bf[nt]);
        }
        __syncthreads();
    }

    #pragma unroll
    for (int mt = 0; mt < MT; mt++) {
        int r0 = rowBase + warpM * WM + mt * 16 + g;
        #pragma unroll
        for (int nt = 0; nt < 8; nt++) {
            int c0 = warpN * 64 + nt * 8 + tg * 2;
            float b0 = __ldg(bp_ + c0), b1 = __ldg(bp_ + c0 + 1);
            if (r0 < M)
                *(__half2*)(Mout + (size_t)r0 * 128 + c0) =
                    __floats2half2_rn(fmaxf(acc[mt][nt][0] + b0, 0.f), fmaxf(acc[mt][nt][1] + b1, 0.f));
            if (r0 + 8 < M)
                *(__half2*)(Mout + (size_t)(r0 + 8) * 128 + c0) =
                    __floats2half2_rn(fmaxf(acc[mt][nt][2] + b0, 0.f), fmaxf(acc[mt][nt][3] + b1, 0.f));
        }
    }
}

// ---------------- launch ----------------------------------------------------
extern "C" void kernel_launch(void* const* d_in, const int* in_sizes, int n_in,
                              void* d_out, int out_size) {
    const float* x    = (const float*)d_in[0];
    const int*   esrc = (const int*)d_in[1];
    const int*   edst = (const int*)d_in[2];
    const float *Wp[3], *bp[3], *Ws[3], *Wn[3], *bn[3];
    for (int l = 0; l < 3; l++) {
        Wp[l] = (const float*)d_in[3 + 5 * l + 0];
        bp[l] = (const float*)d_in[3 + 5 * l + 1];
        Ws[l] = (const float*)d_in[3 + 5 * l + 2];
        Wn[l] = (const float*)d_in[3 + 5 * l + 3];
        bn[l] = (const float*)d_in[3 + 5 * l + 4];
    }
    const int M = N_NODES;

    __half *p_xh, *p_mh, *p_mh2, *p_h1h, *p_h2h, *p_w;
    cudaGetSymbolAddress((void**)&p_xh,  g_xh);
    cudaGetSymbolAddress((void**)&p_mh,  g_mh);
    cudaGetSymbolAddress((void**)&p_mh2, g_mh2);
    cudaGetSymbolAddress((void**)&p_h1h, g_h1h);
    cudaGetSymbolAddress((void**)&p_h2h, g_h2h);
    cudaGetSymbolAddress((void**)&p_w,   g_wt);
    const __half* WpT[3] = { p_w +      0, p_w +  16384, p_w +  32768 };
    const __half* WsT[3] = { p_w +  49152, p_w +  65536, p_w +  81920 };
    const __half* WnT[3] = { p_w +  90112, p_w + 106496, p_w + 122880 };

    const int SMEM128 = (8704 + 5120 + 2 * 128 * 20) * 4;   // 75776 B
    const int SMEM64  = (8704 + 5120 + 2 * 64 * 20) * 4;    // 65536 B
    cudaFuncSetAttribute(comb_kernel<128, true>,
                         cudaFuncAttributeMaxDynamicSharedMemorySize, SMEM128);
    cudaFuncSetAttribute(comb_kernel<64, false>,
                         cudaFuncAttributeMaxDynamicSharedMemorySize, SMEM64);

    // prep (weights^T, x->fp16, zero counts) + CSR build
    prep_kernel<<<7153, 256>>>(Wp[0], Wp[1], Wp[2], Ws[0], Ws[1], Ws[2],
                               Wn[0], Wn[1], Wn[2], (const float4*)x);
    hist_kernel<<<(N_EDGES / 4 + 255) / 256, 256>>>((const int4*)edst);
    reduce_counts_kernel<<<NBLK, 256>>>();
    scan_partials_kernel<<<1, 512>>>();
    write_offsets_kernel<<<NBLK, 256>>>();
    fill_kernel<<<(N_EDGES / 4 + 255) / 256, 256>>>((const int4*)esrc, (const int4*)edst);

    // layer chain: pool0, then fused combine(+next pool) per layer.
    // Pooled-feature buffers ping-pong (Min != Mout) to avoid cross-block races.
    pool_kernel<<<GBLK, 256>>>(p_xh, WpT[0], bp[0], p_mh, M);
    comb_kernel<128, true><<<GBLK, 256, SMEM128>>>(
        p_mh,  p_xh,  WsT[0], WnT[0], bn[0], WpT[1], bp[1], p_h1h, p_mh2, nullptr, M);
    comb_kernel<128, true><<<GBLK, 256, SMEM128>>>(
        p_mh2, p_h1h, WsT[1], WnT[1], bn[1], WpT[2], bp[2], p_h2h, p_mh,  nullptr, M);
    comb_kernel<64, false><<<GBLK, 256, SMEM64>>>(
        p_mh,  p_h2h, WsT[2], WnT[2], bn[2], nullptr, nullptr, nullptr, nullptr,
        (float*)d_out, M);
}